// round 12
// baseline (speedup 1.0000x reference)
#include <cuda_runtime.h>
#include <cuda_bf16.h>
#include <math.h>
#include <stdint.h>

#define NN 100000
#define KK 20
#define DD 96
#define HH 1024
#define CC 7
#define KPAD 100096               // 1564 * 64 = 782 * 128
#define NCHK (KPAD / 64)          // 1564
#define GSPLIT 4
#define CPT (NCHK / GSPLIT)       // 391 k-chunks per split
#define NTRI 36
#define NCHUNK 32
#define NPER (NN / NCHUNK)        // 3125

// gram smem geometry: 4 tiles of 128 rows x 72 bf16 (64 used + 8 pad), double buffered
#define GS_ROWB 144               // bytes per padded row
#define GS_TILE (128 * GS_ROWB)   // 18432 B
#define GS_STAGE (4 * GS_TILE)    // 73728 B
#define GS_TOTAL (2 * GS_STAGE)   // 147456 B

// feath smem: As 32x132 f32 + Bs 32x132 f32 + sT 128x72 f32
#define FA_STRIDE 132
#define FT_AS_OFF 0
#define FT_BS_OFF (32 * FA_STRIDE)
#define FT_ST_OFF (2 * 32 * FA_STRIDE)
#define FT_ST_STRIDE 72
#define FT_SMEM ((2 * 32 * FA_STRIDE + 128 * FT_ST_STRIDE) * 4)   // 70656 B

// ---------------- scratch (static device globals; no allocations) ----------------
static __device__ int           d_preds[NN];
static __device__ float         d_maskf[NN];
static __device__ float         d_featH[(long long)NN * HH];        // 400 MB fp32
static __device__ __nv_bfloat16 d_Fhi[(long long)HH * KPAD];        // masked transposed hi
static __device__ __nv_bfloat16 d_Flo[(long long)HH * KPAD];        // masked transposed lo
static __device__ float         d_Spart[GSPLIT * NTRI * 128 * 128]; // split-K partials
static __device__ float         d_Qpart[NCHUNK * HH * CC];
static __device__ float         d_Qn[HH * CC];
static __device__ float         d_Gn[HH * HH];
static __device__ float         d_GA[HH * HH];   // A = G + Gin + ridge (kept for IR)
static __device__ float         d_Gf[HH * HH];   // factored in place (fp32 Cholesky)
static __device__ float         d_dinvf[HH];
static __device__ float         d_res[HH * CC];
static __device__ float         d_wo[HH * CC];

// ---------------- ptx helpers (base-target features only: sm_80+) ----------------
__device__ __forceinline__ uint32_t smem_to_u32(const void* smem_ptr) {
    uint32_t addr;
    asm("{ .reg .u64 tmp; cvta.to.shared.u64 tmp, %1; cvt.u32.u64 %0, tmp; }"
        : "=r"(addr) : "l"(smem_ptr));
    return addr;
}
#define CP_ASYNC16(dst, src) \
    asm volatile("cp.async.cg.shared.global [%0], [%1], 16;" :: "r"(dst), "l"(src))
#define CP_COMMIT() asm volatile("cp.async.commit_group;" ::: "memory")
#define CP_WAIT1()  asm volatile("cp.async.wait_group 1;" ::: "memory")
#define CP_WAIT0()  asm volatile("cp.async.wait_group 0;" ::: "memory")
#define LDSM4(r, addr) \
    asm volatile("ldmatrix.sync.aligned.m8n8.x4.shared.b16 {%0,%1,%2,%3}, [%4];" \
        : "=r"((r)[0]), "=r"((r)[1]), "=r"((r)[2]), "=r"((r)[3]) : "r"(addr))
#define MMA16816(c, a, b) \
    asm volatile("mma.sync.aligned.m16n8k16.row.col.f32.bf16.bf16.f32 " \
        "{%0,%1,%2,%3}, {%4,%5,%6,%7}, {%8,%9}, {%0,%1,%2,%3};" \
        : "+f"((c)[0]), "+f"((c)[1]), "+f"((c)[2]), "+f"((c)[3]) \
        : "r"((a)[0]), "r"((a)[1]), "r"((a)[2]), "r"((a)[3]), "r"((b)[0]), "r"((b)[1]))

// ---------------- f32x2 helpers (feath) ----------------
__device__ __forceinline__ unsigned long long ffma2(unsigned long long a,
                                                    unsigned long long b,
                                                    unsigned long long c) {
    unsigned long long d;
    asm("fma.rn.f32x2 %0, %1, %2, %3;" : "=l"(d) : "l"(a), "l"(b), "l"(c));
    return d;
}
__device__ __forceinline__ unsigned long long dup2(float x) {
    unsigned long long d;
    asm("mov.b64 %0, {%1, %1};" : "=l"(d) : "f"(x));
    return d;
}
__device__ __forceinline__ float2 up2(unsigned long long v) {
    float2 r;
    asm("mov.b64 {%0, %1}, %2;" : "=f"(r.x), "=f"(r.y) : "l"(v));
    return r;
}
__device__ __forceinline__ unsigned long long d2u(double d) {
    return (unsigned long long)__double_as_longlong(d);
}

// ---------------- launch 0: preds (with inline proto normalize) ----------------
__global__ __launch_bounds__(256) void preds_kernel(const float* __restrict__ feat,
                                                    const float* __restrict__ proto) {
    __shared__ float sp[CC][DD];
    int tid = threadIdx.x;
    if (tid < CC) {
        float s = 0.f;
        for (int k = 0; k < DD; k++) { float v = proto[tid * DD + k]; s += v * v; }
        float inv = 1.f / fmaxf(sqrtf(s), 1e-12f);
        for (int k = 0; k < DD; k++) sp[tid][k] = proto[tid * DD + k] * inv;
    }
    __syncthreads();
    int n = blockIdx.x * 256 + tid;
    if (n >= NN) return;
    const float* f = feat + (long long)n * DD;
    float acc[CC];
#pragma unroll
    for (int c = 0; c < CC; c++) acc[c] = 0.f;
#pragma unroll 4
    for (int k = 0; k < DD; k++) {
        float fk = f[k];
#pragma unroll
        for (int c = 0; c < CC; c++) acc[c] += fk * sp[c][k];
    }
    float best = acc[0];
    int bi = 0;
#pragma unroll
    for (int c = 1; c < CC; c++)
        if (acc[c] > best) { best = acc[c]; bi = c; }
    d_preds[n] = bi;
}

// ---------------- launch 1: mask (inline idx-dtype detect) ----------------
__global__ __launch_bounds__(256) void mask_kernel(const float* __restrict__ coords,
                                                   const float* __restrict__ normz,
                                                   const void* __restrict__ nidx) {
    int n = blockIdx.x * 256 + threadIdx.x;
    if (n >= NN) return;
    const int* pw = (const int*)nidx;
    int is64 = 1;
#pragma unroll
    for (int k = 1; k < 40; k += 2) is64 &= (pw[k] == 0);

    int p = d_preds[n];
    const long long* ni64 = (const long long*)nidx;
    const int*       ni32 = (const int*)nidx;
    int cnt = 0;
#pragma unroll
    for (int k = 0; k < KK; k++) {
        long long raw = is64 ? ni64[(long long)n * KK + k]
                             : (long long)ni32[(long long)n * KK + k];
        unsigned int idx = (unsigned int)raw;
        if (idx >= NN) idx = 0;
        cnt += (d_preds[idx] == p);
    }
    bool cmask = cnt > 16;
    bool plane   = (p == 2) | (p == 3) | (p == 4);
    bool manmade = (p == 5);
    bool other   = (p == 0) | (p == 1) | (p == 6);
    float nz = normz[n];
    float z  = coords[(long long)n * 3 + 2];
    bool ground = plane && (nz > 0.9f) && (z < -10.0f);
    bool g = ground || other || manmade;
    bool m = (manmade && (nz < 0.1f)) || other || plane;
    d_maskf[n] = (cmask && g && m) ? 1.f : 0.f;
}

// ---------------- launch 2: feat_h = relu(feat @ W); 128x128 tile, 8x8/thread ----------------
__global__ __launch_bounds__(256, 2) void feath_kernel(const float* __restrict__ feat,
                                                       const float* __restrict__ w) {
    extern __shared__ float fsm[];
    float* As = fsm + FT_AS_OFF;   // [32][132]  As[k][n-local]
    float* Bs = fsm + FT_BS_OFF;   // [32][132]  Bs[k][h-local]
    float* sT = fsm + FT_ST_OFF;   // [128][72]  sT[h-local][n-half-local]
    int tid = threadIdx.x;
    int h0 = blockIdx.x * 128;
    int n0 = blockIdx.y * 128;
    int tx = tid & 15, ty = tid >> 4;

    unsigned long long acc[8][4];
#pragma unroll
    for (int r = 0; r < 8; r++)
#pragma unroll
        for (int c = 0; c < 4; c++) acc[r][c] = 0ull;

    for (int k0 = 0; k0 < DD; k0 += 32) {
        for (int i = tid; i < 4096; i += 256) {          // As: 128n x 32k
            int k = i & 31, m = i >> 5;
            int n = n0 + m;
            As[k * FA_STRIDE + m] = (n < NN) ? feat[(long long)n * DD + k0 + k] : 0.f;
        }
        for (int i = tid; i < 4096; i += 256) {          // Bs: 32k x 128h
            int k = i >> 7, m = i & 127;
            Bs[k * FA_STRIDE + m] = w[(k0 + k) * HH + h0 + m];
        }
        __syncthreads();
#pragma unroll
        for (int k = 0; k < 32; k++) {
            float4 a0 = *reinterpret_cast<const float4*>(&As[k * FA_STRIDE + ty * 8]);
            float4 a1 = *reinterpret_cast<const float4*>(&As[k * FA_STRIDE + ty * 8 + 4]);
            double2 b0 = *reinterpret_cast<const double2*>(&Bs[k * FA_STRIDE + tx * 8]);
            double2 b1 = *reinterpret_cast<const double2*>(&Bs[k * FA_STRIDE + tx * 8 + 4]);
            unsigned long long bp0 = d2u(b0.x), bp1 = d2u(b0.y);
            unsigned long long bp2 = d2u(b1.x), bp3 = d2u(b1.y);
            float av[8] = {a0.x, a0.y, a0.z, a0.w, a1.x, a1.y, a1.z, a1.w};
#pragma unroll
            for (int rn = 0; rn < 8; rn++) {
                unsigned long long ap = dup2(av[rn]);
                acc[rn][0] = ffma2(ap, bp0, acc[rn][0]);
                acc[rn][1] = ffma2(ap, bp1, acc[rn][1]);
                acc[rn][2] = ffma2(ap, bp2, acc[rn][2]);
                acc[rn][3] = ffma2(ap, bp3, acc[rn][3]);
            }
        }
        __syncthreads();
    }

    // relu into vr[n][h], fp32 global write (coalesced by h)
    float vr[8][8];
#pragma unroll
    for (int rn = 0; rn < 8; rn++) {
#pragma unroll
        for (int c4 = 0; c4 < 4; c4++) {
            float2 f = up2(acc[rn][c4]);
            vr[rn][c4 * 2]     = fmaxf(f.x, 0.f);
            vr[rn][c4 * 2 + 1] = fmaxf(f.y, 0.f);
        }
        int n = n0 + ty * 8 + rn;
        if (n < NN) {
            float* dst = &d_featH[(long long)n * HH + h0 + tx * 8];
            *reinterpret_cast<float4*>(dst) =
                make_float4(vr[rn][0], vr[rn][1], vr[rn][2], vr[rn][3]);
            *reinterpret_cast<float4*>(dst + 4) =
                make_float4(vr[rn][4], vr[rn][5], vr[rn][6], vr[rn][7]);
        }
    }

    // transposed masked bf16 hi/lo writes, in two 64-column halves via sT
    __nv_bfloat16 zero = __float2bfloat16(0.f);
#pragma unroll
    for (int half = 0; half < 2; half++) {
        __syncthreads();
        if ((ty >> 3) == half) {
            int tyl = ty & 7;
#pragma unroll
            for (int c = 0; c < 8; c++) {
                int row = tx * 8 + c;
                uint32_t sw = ((uint32_t)(tx & 3)) << 3;
#pragma unroll
                for (int rn = 0; rn < 8; rn++) {
                    uint32_t col = (uint32_t)(tyl * 8 + rn) ^ sw;
                    sT[row * FT_ST_STRIDE + col] = vr[rn][c];
                }
            }
        }
        __syncthreads();
        {
            int hrow = tid >> 1, seg = tid & 1;
            int nbase = n0 + half * 64 + seg * 32;
            uint32_t sw = ((uint32_t)((hrow >> 3) & 3)) << 3;
            __align__(16) __nv_bfloat16 hb[32], lb[32];
#pragma unroll
            for (int j = 0; j < 32; j++) {
                int nl = seg * 32 + j;
                float v = sT[hrow * FT_ST_STRIDE + (((uint32_t)nl) ^ sw)];
                int n = nbase + j;
                bool mk = (n < NN) && (d_maskf[n] != 0.f);
                __nv_bfloat16 hv = __float2bfloat16(v);
                hb[j] = mk ? hv : zero;
                lb[j] = mk ? __float2bfloat16(v - __bfloat162float(hv)) : zero;
            }
            size_t gb = (size_t)(h0 + hrow) * KPAD + nbase;
#pragma unroll
            for (int q = 0; q < 4; q++) {
                *reinterpret_cast<uint4*>(&d_Fhi[gb + q * 8]) =
                    *reinterpret_cast<uint4*>(&hb[q * 8]);
                *reinterpret_cast<uint4*>(&d_Flo[gb + q * 8]) =
                    *reinterpret_cast<uint4*>(&lb[q * 8]);
            }
        }
    }
}

// ---------------- launch 3 (ncu slot): Gram via mma.sync bf16 hi/lo, split-K ----------------
__global__ __launch_bounds__(512, 1) void gram_hmma_kernel() {
    extern __shared__ __align__(16) char smg[];
    uint32_t sb = smem_to_u32(smg);
    int tid = threadIdx.x;
    int t = blockIdx.x, sp = blockIdx.y;
    int bi = 0;
    while ((bi + 1) * (bi + 2) / 2 <= t) bi++;
    int bj = t - bi * (bi + 1) / 2;
    int h10 = bi * 128, h20 = bj * 128;

    int lrow = tid >> 2, lseg = tid & 3;
    size_t kstart = (size_t)sp * CPT * 64 + lseg * 16;
    const __nv_bfloat16* pAh = d_Fhi + (size_t)(h10 + lrow) * KPAD + kstart;
    const __nv_bfloat16* pAl = d_Flo + (size_t)(h10 + lrow) * KPAD + kstart;
    const __nv_bfloat16* pBh = d_Fhi + (size_t)(h20 + lrow) * KPAD + kstart;
    const __nv_bfloat16* pBl = d_Flo + (size_t)(h20 + lrow) * KPAD + kstart;
    uint32_t ldst = sb + lrow * GS_ROWB + lseg * 32;

    int wid = tid >> 5, lane = tid & 31;
    int mbase = (wid >> 2) * 32, nbase = (wid & 3) * 32;
    int arow = (lane & 7) + ((lane >> 3) & 1) * 8;
    int acol = ((lane >> 4) & 1) * 8;
    int brow = (lane & 7) + ((lane >> 4) & 1) * 8;
    int bcol = ((lane >> 3) & 1) * 8;
    uint32_t aoff[2], boff[2];
#pragma unroll
    for (int mi = 0; mi < 2; mi++)
        aoff[mi] = (uint32_t)(((mbase + mi * 16 + arow) * 72 + acol) * 2);
#pragma unroll
    for (int nj = 0; nj < 2; nj++)
        boff[nj] = (uint32_t)(((nbase + nj * 16 + brow) * 72 + bcol) * 2);

    float acc[2][4][4];
#pragma unroll
    for (int a = 0; a < 2; a++)
#pragma unroll
        for (int b = 0; b < 4; b++)
#pragma unroll
            for (int c = 0; c < 4; c++) acc[a][b][c] = 0.f;

    {
        uint32_t base = ldst;
#pragma unroll
        for (int j = 0; j < 2; j++) {
            CP_ASYNC16(base + 0 * GS_TILE + j * 16, pAh + j * 8);
            CP_ASYNC16(base + 1 * GS_TILE + j * 16, pAl + j * 8);
            CP_ASYNC16(base + 2 * GS_TILE + j * 16, pBh + j * 8);
            CP_ASYNC16(base + 3 * GS_TILE + j * 16, pBl + j * 8);
        }
        CP_COMMIT();
    }

    for (int c = 0; c < CPT; c++) {
        if (c + 1 < CPT) {
            uint32_t base = ldst + ((c + 1) & 1) * GS_STAGE;
            size_t ko = (size_t)(c + 1) * 64;
#pragma unroll
            for (int j = 0; j < 2; j++) {
                CP_ASYNC16(base + 0 * GS_TILE + j * 16, pAh + ko + j * 8);
                CP_ASYNC16(base + 1 * GS_TILE + j * 16, pAl + ko + j * 8);
                CP_ASYNC16(base + 2 * GS_TILE + j * 16, pBh + ko + j * 8);
                CP_ASYNC16(base + 3 * GS_TILE + j * 16, pBl + ko + j * 8);
            }
            CP_COMMIT();
            CP_WAIT1();
        } else {
            CP_WAIT0();
        }
        __syncthreads();
        uint32_t stg = sb + (c & 1) * GS_STAGE;
#pragma unroll
        for (int ks = 0; ks < 4; ks++) {
            uint32_t kb = ks * 32;
            uint32_t ah[2][4], al[2][4], bh[4][2], bl[4][2];
#pragma unroll
            for (int mi = 0; mi < 2; mi++)
                LDSM4(ah[mi], stg + 0 * GS_TILE + aoff[mi] + kb);
#pragma unroll
            for (int nj = 0; nj < 2; nj++) {
                uint32_t r[4];
                LDSM4(r, stg + 2 * GS_TILE + boff[nj] + kb);
                bh[nj * 2][0] = r[0]; bh[nj * 2][1] = r[1];
                bh[nj * 2 + 1][0] = r[2]; bh[nj * 2 + 1][1] = r[3];
            }
#pragma unroll
            for (int mi = 0; mi < 2; mi++)
#pragma unroll
                for (int nj = 0; nj < 4; nj++) MMA16816(acc[mi][nj], ah[mi], bh[nj]);
#pragma unroll
            for (int nj = 0; nj < 2; nj++) {
                uint32_t r[4];
                LDSM4(r, stg + 3 * GS_TILE + boff[nj] + kb);
                bl[nj * 2][0] = r[0]; bl[nj * 2][1] = r[1];
                bl[nj * 2 + 1][0] = r[2]; bl[nj * 2 + 1][1] = r[3];
            }
#pragma unroll
            for (int mi = 0; mi < 2; mi++)
#pragma unroll
                for (int nj = 0; nj < 4; nj++) MMA16816(acc[mi][nj], ah[mi], bl[nj]);
#pragma unroll
            for (int mi = 0; mi < 2; mi++)
                LDSM4(al[mi], stg + 1 * GS_TILE + aoff[mi] + kb);
#pragma unroll
            for (int mi = 0; mi < 2; mi++)
#pragma unroll
                for (int nj = 0; nj < 4; nj++) MMA16816(acc[mi][nj], al[mi], bh[nj]);
        }
        __syncthreads();
    }

    float* out = &d_Spart[(size_t)(sp * NTRI + t) * 128 * 128];
    int g = lane >> 2, q = lane & 3;
#pragma unroll
    for (int mi = 0; mi < 2; mi++) {
#pragma unroll
        for (int nj = 0; nj < 4; nj++) {
            int r0 = mbase + mi * 16 + g;
            int cc = nbase + nj * 8 + q * 2;
            *reinterpret_cast<float2*>(&out[r0 * 128 + cc]) =
                make_float2(acc[mi][nj][0], acc[mi][nj][1]);
            *reinterpret_cast<float2*>(&out[(r0 + 8) * 128 + cc]) =
                make_float2(acc[mi][nj][2], acc[mi][nj][3]);
        }
    }
}

// ---------------- reduce split-K partials into d_Gn lower triangle ----------------
__global__ __launch_bounds__(256) void greduce_kernel() {
    int t = blockIdx.x;
    int bi = 0;
    while ((bi + 1) * (bi + 2) / 2 <= t) bi++;
    int bj = t - bi * (bi + 1) / 2;
    for (int i = threadIdx.x; i < 128 * 128 / 4; i += 256) {
        float4 s = make_float4(0.f, 0.f, 0.f, 0.f);
#pragma unroll
        for (int sp = 0; sp < GSPLIT; sp++) {
            float4 v = *reinterpret_cast<const float4*>(
                &d_Spart[(size_t)(sp * NTRI + t) * 128 * 128 + i * 4]);
            s.x += v.x; s.y += v.y; s.z += v.z; s.w += v.w;
        }
        int r = (i * 4) >> 7, c = (i * 4) & 127;
        *reinterpret_cast<float4*>(&d_Gn[(bi * 128 + r) * HH + bj * 128 + c]) = s;
    }
}

// ---------------- Qn partials: branchless, unroll-5 for MLP ----------------
__global__ __launch_bounds__(256) void qpart_kernel() {
    int h = blockIdx.x * 256 + threadIdx.x;
    int chunk = blockIdx.y;
    int nb = chunk * NPER;
    float a[CC];
#pragma unroll
    for (int c = 0; c < CC; c++) a[c] = 0.f;
    for (int t = 0; t < NPER; t += 5) {
#pragma unroll
        for (int u = 0; u < 5; u++) {
            int n = nb + t + u;
            float mv = d_maskf[n];
            float v = d_featH[(long long)n * HH + h] * mv;
            int p = d_preds[n];
            a[0] += (p == 0) ? v : 0.f;
            a[1] += (p == 1) ? v : 0.f;
            a[2] += (p == 2) ? v : 0.f;
            a[3] += (p == 3) ? v : 0.f;
            a[4] += (p == 4) ? v : 0.f;
            a[5] += (p == 5) ? v : 0.f;
            a[6] += (p == 6) ? v : 0.f;
        }
    }
    int o = (chunk * HH + h) * CC;
#pragma unroll
    for (int c = 0; c < CC; c++) d_Qpart[o + c] = a[c];
}

__global__ void qreduce_kernel(const float* __restrict__ Qin) {
    int idx = blockIdx.x * 256 + threadIdx.x;
    if (idx >= HH * CC) return;
    float s = Qin[idx];
    for (int ch = 0; ch < NCHUNK; ch++) s += d_Qpart[ch * HH * CC + idx];
    d_Qn[idx] = s;
}

// ---------------- mirror + Gin + ridge -> fp32 A (two copies) ----------------
__global__ void convm_kernel(const float* __restrict__ Gin) {
    int idx = blockIdx.x * 256 + threadIdx.x;
    int i = idx >> 10, j = idx & 1023;
    float v = (i >= j) ? d_Gn[i * HH + j] : d_Gn[j * HH + i];
    float a = v + Gin[idx] + ((i == j) ? 100.0f : 0.0f);
    d_GA[idx] = a;
    d_Gf[idx] = a;
}

// ---------------- blocked fp32 Cholesky (lower), block = 64 ----------------
__global__ void chol_potf2(int kb) {
    int i = threadIdx.x;
    int off = kb * 64;
    __shared__ float s[64][65];
    for (int j = 0; j < 64; j++) s[i][j] = d_Gf[(off + i) * HH + off + j];
    __syncthreads();
    for (int j = 0; j < 64; j++) {
        if (i == j) s[j][j] = sqrtf(fmaxf(s[j][j], 1e-20f));
        __syncthreads();
        if (i > j) s[i][j] /= s[j][j];
        __syncthreads();
        if (i > j) {
            float lij = s[i][j];
            for (int k = j + 1; k <= i; k++) s[i][k] -= lij * s[k][j];
        }
        __syncthreads();
    }
    for (int j = 0; j <= i; j++) d_Gf[(off + i) * HH + off + j] = s[i][j];
    d_dinvf[off + i] = 1.0f / s[i][i];
}

__global__ __launch_bounds__(256) void chol_trsm(int kb) {
    int off = kb * 64;
    int base = off + 64;
    __shared__ float L[64][65];
    __shared__ float di[64];
    for (int i = threadIdx.x; i < 64 * 64; i += 256)
        L[i >> 6][i & 63] = d_Gf[(off + (i >> 6)) * HH + off + (i & 63)];
    if (threadIdx.x < 64) di[threadIdx.x] = d_dinvf[off + threadIdx.x];
    __syncthreads();
    int r = base + blockIdx.x * 256 + threadIdx.x;
    if (r >= HH) return;
    float* a = &d_Gf[r * HH + off];
    float x[64];
#pragma unroll
    for (int j = 0; j < 64; j++) x[j] = a[j];
#pragma unroll
    for (int j = 0; j < 64; j++) {
        float xj = x[j] * di[j];
        x[j] = xj;
#pragma unroll
        for (int tt = j + 1; tt < 64; tt++) x[tt] -= xj * L[tt][j];
    }
#pragma unroll
    for (int j = 0; j < 64; j++) a[j] = x[j];
}

__global__ __launch_bounds__(256) void chol_syrk(int kb) {
    int off = kb * 64;
    int base = off + 64;
    int i0 = base + blockIdx.y * 32;
    int j0 = base + blockIdx.x * 32;
    if (j0 > i0) return;
    __shared__ float Li[32][65];
    __shared__ float Lj[32][65];
    int tid = threadIdx.x;
    for (int i = tid; i < 32 * 64; i += 256) {
        int ii = i >> 6, t = i & 63;
        Li[ii][t] = d_Gf[(i0 + ii) * HH + off + t];
        Lj[ii][t] = d_Gf[(j0 + ii) * HH + off + t];
    }
    __syncthreads();
    int tx = tid & 31, ty = tid >> 5;
    float acc[4] = {0, 0, 0, 0};
    for (int t = 0; t < 64; t++) {
        float bj = Lj[tx][t];
#pragma unroll
        for (int r = 0; r < 4; r++) acc[r] += Li[(ty << 2) + r][t] * bj;
    }
#pragma unroll
    for (int r = 0; r < 4; r++) {
        int i = i0 + (ty << 2) + r;
        int j = j0 + tx;
        if (j <= i) d_Gf[i * HH + j] -= acc[r];
    }
}

// ---------------- triangular solves: L y = b ; L^T x = y (7 RHS); mode 0: wo=x, 1: wo+=x, b=res ----------------
__global__ __launch_bounds__(1024) void chol_solve(int mode) {
    int i = threadIdx.x;
    __shared__ float shy[64][CC];
    float y[CC];
    const float* b = (mode == 0) ? d_Qn : d_res;
#pragma unroll
    for (int c = 0; c < CC; c++) y[c] = b[i * CC + c];
    for (int jb = 0; jb < HH; jb += 64) {
        for (int j = jb; j < jb + 64; j++) {
            if (i == j) {
                float dgl = d_dinvf[j];
#pragma unroll
                for (int c = 0; c < CC; c++) { y[c] *= dgl; shy[j - jb][c] = y[c]; }
            }
            __syncthreads();
            if (i > j && i < jb + 64) {
                float lij = d_Gf[i * HH + j];
#pragma unroll
                for (int c = 0; c < CC; c++) y[c] -= lij * shy[j - jb][c];
            }
            __syncthreads();
        }
        if (i >= jb + 64) {
            for (int t = 0; t < 64; t++) {
                float lij = d_Gf[i * HH + jb + t];
#pragma unroll
                for (int c = 0; c < CC; c++) y[c] -= lij * shy[t][c];
            }
        }
        __syncthreads();
    }
    for (int jb = HH - 64; jb >= 0; jb -= 64) {
        for (int j = jb + 63; j >= jb; j--) {
            if (i == j) {
                float dgl = d_dinvf[j];
#pragma unroll
                for (int c = 0; c < CC; c++) { y[c] *= dgl; shy[j - jb][c] = y[c]; }
            }
            __syncthreads();
            if (i >= jb && i < j) {
                float lji = d_Gf[j * HH + i];
#pragma unroll
                for (int c = 0; c < CC; c++) y[c] -= lji * shy[j - jb][c];
            }
            __syncthreads();
        }
        if (i < jb) {
            for (int t = 0; t < 64; t++) {
                float lji = d_Gf[(jb + t) * HH + i];
#pragma unroll
                for (int c = 0; c < CC; c++) y[c] -= lji * shy[t][c];
            }
        }
        __syncthreads();
    }
    if (mode == 0) {
#pragma unroll
        for (int c = 0; c < CC; c++) d_wo[i * CC + c] = y[c];
    } else {
#pragma unroll
        for (int c = 0; c < CC; c++) d_wo[i * CC + c] += y[c];
    }
}

// ---------------- residual r = Qn - A*wo, fp32 TwoProd + Neumaier compensation ----------------
__global__ __launch_bounds__(256) void resid_kernel() {
    __shared__ float sw[HH * CC];
    int tid = threadIdx.x;
    for (int i = tid; i < HH * CC; i += 256) sw[i] = d_wo[i];
    __syncthreads();
    int wid = tid >> 5, lane = tid & 31;
    int row = blockIdx.x * 8 + wid;
    float s[CC], comp[CC];
#pragma unroll
    for (int c = 0; c < CC; c++) {
        s[c] = (lane == 0) ? d_Qn[row * CC + c] : 0.f;
        comp[c] = 0.f;
    }
    const float* arow = &d_GA[row * HH];
    for (int j = lane; j < HH; j += 32) {
        float na = -arow[j];
#pragma unroll
        for (int c = 0; c < CC; c++) {
            float w = sw[j * CC + c];
            float p = na * w;
            float e = fmaf(na, w, -p);
            float t = s[c] + p;
            float bb = t - s[c];
            float err = (s[c] - (t - bb)) + (p - bb);
            s[c] = t;
            comp[c] += err + e;
        }
    }
#pragma unroll
    for (int c = 0; c < CC; c++) {
#pragma unroll
        for (int off = 16; off > 0; off >>= 1) {
            float s2 = __shfl_xor_sync(0xffffffffu, s[c], off);
            float c2 = __shfl_xor_sync(0xffffffffu, comp[c], off);
            float t = s[c] + s2;
            float bb = t - s[c];
            float err = (s[c] - (t - bb)) + (s2 - bb);
            s[c] = t;
            comp[c] += c2 + err;
        }
    }
    if (lane == 0) {
#pragma unroll
        for (int c = 0; c < CC; c++) d_res[row * CC + c] = s[c] + comp[c];
    }
}

// ---------------- pred_domain = featH @ wo ----------------
__global__ __launch_bounds__(256) void final_kernel(float* __restrict__ out) {
    __shared__ float sw[HH * CC];
    int tid = threadIdx.x;
    for (int i = tid; i < HH * CC; i += 256) sw[i] = d_wo[i];
    __syncthreads();
    int warp = tid >> 5, lane = tid & 31;
    int n = blockIdx.x * 8 + warp;
    if (n >= NN) return;
    const float* a = &d_featH[(long long)n * HH];
    float acc[CC];
#pragma unroll
    for (int c = 0; c < CC; c++) acc[c] = 0.f;
#pragma unroll
    for (int h = lane; h < HH; h += 32) {
        float v = a[h];
#pragma unroll
        for (int c = 0; c < CC; c++) acc[c] += v * sw[h * CC + c];
    }
#pragma unroll
    for (int c = 0; c < CC; c++) {
#pragma unroll
        for (int off = 16; off > 0; off >>= 1)
            acc[c] += __shfl_xor_sync(0xffffffffu, acc[c], off);
    }
    if (lane == 0) {
#pragma unroll
        for (int c = 0; c < CC; c++) out[(long long)n * CC + c] = acc[c];
    }
}

// ---------------- launcher ----------------
extern "C" void kernel_launch(void* const* d_in, const int* in_sizes, int n_in,
                              void* d_out, int out_size) {
    const float* feat   = (const float*)d_in[0];
    const float* proto  = (const float*)d_in[1];
    const float* wrand  = (const float*)d_in[2];
    const float* Qin    = (const float*)d_in[3];
    const float* Gin    = (const float*)d_in[4];
    const float* coords = (const float*)d_in[5];
    const float* normz  = (const float*)d_in[6];
    const void*  nidx   = (const void*)d_in[7];
    float* out = (float*)d_out;

    cudaFuncSetAttribute(gram_hmma_kernel,
                         cudaFuncAttributeMaxDynamicSharedMemorySize, GS_TOTAL);
    cudaFuncSetAttribute(feath_kernel,
                         cudaFuncAttributeMaxDynamicSharedMemorySize, FT_SMEM);

    preds_kernel<<<(NN + 255) / 256, 256>>>(feat, proto);                 // 0
    mask_kernel<<<(NN + 255) / 256, 256>>>(coords, normz, nidx);          // 1
    feath_kernel<<<dim3(HH / 128, KPAD / 128), 256, FT_SMEM>>>(feat, wrand); // 2
    gram_hmma_kernel<<<dim3(NTRI, GSPLIT), 512, GS_TOTAL>>>();            // 3 <- ncu slot
    greduce_kernel<<<NTRI, 256>>>();
    qpart_kernel<<<dim3(HH / 256, NCHUNK), 256>>>();
    qreduce_kernel<<<(HH * CC + 255) / 256, 256>>>(Qin);
    convm_kernel<<<(HH * HH) / 256, 256>>>(Gin);

    for (int kb = 0; kb < HH / 64; kb++) {
        chol_potf2<<<1, 64>>>(kb);
        int rows = HH - (kb * 64 + 64);
        if (rows > 0) {
            chol_trsm<<<(rows + 255) / 256, 256>>>(kb);
            int nt = (rows + 31) / 32;
            chol_syrk<<<dim3(nt, nt), 256>>>(kb);
        }
    }
    chol_solve<<<1, 1024>>>(0);
    resid_kernel<<<HH / 8, 256>>>();
    chol_solve<<<1, 1024>>>(1);
    resid_kernel<<<HH / 8, 256>>>();
    chol_solve<<<1, 1024>>>(1);
    final_kernel<<<(NN + 7) / 8, 256>>>(out);
}

// round 13
// speedup vs baseline: 1.2798x; 1.2798x over previous
#include <cuda_runtime.h>
#include <cuda_bf16.h>
#include <math.h>
#include <stdint.h>

#define NN 100000
#define KK 20
#define DD 96
#define HH 1024
#define CC 7
#define KPAD 100096               // 1564 * 64
#define NCHK (KPAD / 64)          // 1564
#define GSPLIT 4
#define CPT (NCHK / GSPLIT)       // 391 k-chunks per split
#define NTRI 36
#define NCHUNK 32
#define NPER (NN / NCHUNK)        // 3125

// gram smem geometry: 4 tiles of 128 rows x 72 bf16 (64 used + 8 pad), double buffered
#define GS_ROWB 144               // bytes per padded row
#define GS_TILE (128 * GS_ROWB)   // 18432 B
#define GS_STAGE (4 * GS_TILE)    // 73728 B
#define GS_TOTAL (2 * GS_STAGE)   // 147456 B

// ---------------- scratch (static device globals; no allocations) ----------------
static __device__ int           d_preds[NN];
static __device__ float         d_maskf[NN];
static __device__ float         d_featH[(long long)NN * HH];        // 400 MB fp32
static __device__ __nv_bfloat16 d_Fhi[(long long)HH * KPAD];        // masked transposed hi
static __device__ __nv_bfloat16 d_Flo[(long long)HH * KPAD];        // masked transposed lo
static __device__ float         d_Spart[GSPLIT * NTRI * 128 * 128]; // split-K partials
static __device__ float         d_Qpart[NCHUNK * HH * CC];
static __device__ float         d_Qn[HH * CC];
static __device__ float         d_Gn[HH * HH];
static __device__ float         d_GA[HH * HH];   // A = G + Gin + ridge (kept for IR)
static __device__ float         d_Gf[HH * HH];   // factored in place (fp32 Cholesky)
static __device__ float         d_dinvf[HH];
static __device__ float         d_res[HH * CC];
static __device__ float         d_wo[HH * CC];

// ---------------- ptx helpers (base-target features only: sm_80+) ----------------
__device__ __forceinline__ uint32_t smem_to_u32(const void* smem_ptr) {
    uint32_t addr;
    asm("{ .reg .u64 tmp; cvta.to.shared.u64 tmp, %1; cvt.u32.u64 %0, tmp; }"
        : "=r"(addr) : "l"(smem_ptr));
    return addr;
}
#define CP_ASYNC16(dst, src) \
    asm volatile("cp.async.cg.shared.global [%0], [%1], 16;" :: "r"(dst), "l"(src))
#define CP_COMMIT() asm volatile("cp.async.commit_group;" ::: "memory")
#define CP_WAIT1()  asm volatile("cp.async.wait_group 1;" ::: "memory")
#define CP_WAIT0()  asm volatile("cp.async.wait_group 0;" ::: "memory")
#define LDSM4(r, addr) \
    asm volatile("ldmatrix.sync.aligned.m8n8.x4.shared.b16 {%0,%1,%2,%3}, [%4];" \
        : "=r"((r)[0]), "=r"((r)[1]), "=r"((r)[2]), "=r"((r)[3]) : "r"(addr))
#define MMA16816(c, a, b) \
    asm volatile("mma.sync.aligned.m16n8k16.row.col.f32.bf16.bf16.f32 " \
        "{%0,%1,%2,%3}, {%4,%5,%6,%7}, {%8,%9}, {%0,%1,%2,%3};" \
        : "+f"((c)[0]), "+f"((c)[1]), "+f"((c)[2]), "+f"((c)[3]) \
        : "r"((a)[0]), "r"((a)[1]), "r"((a)[2]), "r"((a)[3]), "r"((b)[0]), "r"((b)[1]))

// ---------------- f32x2 helpers (feath) ----------------
__device__ __forceinline__ unsigned long long ffma2(unsigned long long a,
                                                    unsigned long long b,
                                                    unsigned long long c) {
    unsigned long long d;
    asm("fma.rn.f32x2 %0, %1, %2, %3;" : "=l"(d) : "l"(a), "l"(b), "l"(c));
    return d;
}
__device__ __forceinline__ unsigned long long dup2(float x) {
    unsigned long long d;
    asm("mov.b64 %0, {%1, %1};" : "=l"(d) : "f"(x));
    return d;
}
__device__ __forceinline__ float2 up2(unsigned long long v) {
    float2 r;
    asm("mov.b64 {%0, %1}, %2;" : "=f"(r.x), "=f"(r.y) : "l"(v));
    return r;
}
__device__ __forceinline__ unsigned long long d2u(double d) {
    return (unsigned long long)__double_as_longlong(d);
}

// ---------------- launch 0: preds (with inline proto normalize) ----------------
__global__ __launch_bounds__(256) void preds_kernel(const float* __restrict__ feat,
                                                    const float* __restrict__ proto) {
    __shared__ float sp[CC][DD];
    int tid = threadIdx.x;
    if (tid < CC) {
        float s = 0.f;
        for (int k = 0; k < DD; k++) { float v = proto[tid * DD + k]; s += v * v; }
        float inv = 1.f / fmaxf(sqrtf(s), 1e-12f);
        for (int k = 0; k < DD; k++) sp[tid][k] = proto[tid * DD + k] * inv;
    }
    __syncthreads();
    int n = blockIdx.x * 256 + tid;
    if (n >= NN) return;
    const float* f = feat + (long long)n * DD;
    float acc[CC];
#pragma unroll
    for (int c = 0; c < CC; c++) acc[c] = 0.f;
#pragma unroll 4
    for (int k = 0; k < DD; k++) {
        float fk = f[k];
#pragma unroll
        for (int c = 0; c < CC; c++) acc[c] += fk * sp[c][k];
    }
    float best = acc[0];
    int bi = 0;
#pragma unroll
    for (int c = 1; c < CC; c++)
        if (acc[c] > best) { best = acc[c]; bi = c; }
    d_preds[n] = bi;
}

// ---------------- launch 1: mask (inline idx-dtype detect) ----------------
__global__ __launch_bounds__(256) void mask_kernel(const float* __restrict__ coords,
                                                   const float* __restrict__ normz,
                                                   const void* __restrict__ nidx) {
    int n = blockIdx.x * 256 + threadIdx.x;
    if (n >= NN) return;
    const int* pw = (const int*)nidx;
    int is64 = 1;
#pragma unroll
    for (int k = 1; k < 40; k += 2) is64 &= (pw[k] == 0);

    int p = d_preds[n];
    const long long* ni64 = (const long long*)nidx;
    const int*       ni32 = (const int*)nidx;
    int cnt = 0;
#pragma unroll
    for (int k = 0; k < KK; k++) {
        long long raw = is64 ? ni64[(long long)n * KK + k]
                             : (long long)ni32[(long long)n * KK + k];
        unsigned int idx = (unsigned int)raw;
        if (idx >= NN) idx = 0;
        cnt += (d_preds[idx] == p);
    }
    bool cmask = cnt > 16;
    bool plane   = (p == 2) | (p == 3) | (p == 4);
    bool manmade = (p == 5);
    bool other   = (p == 0) | (p == 1) | (p == 6);
    float nz = normz[n];
    float z  = coords[(long long)n * 3 + 2];
    bool ground = plane && (nz > 0.9f) && (z < -10.0f);
    bool g = ground || other || manmade;
    bool m = (manmade && (nz < 0.1f)) || other || plane;
    d_maskf[n] = (cmask && g && m) ? 1.f : 0.f;
}

// ---------------- launch 2: feat_h = relu(feat @ W); R11 64x64 version ----------------
__global__ __launch_bounds__(256) void feath_kernel(const float* __restrict__ feat,
                                                    const float* __restrict__ w) {
    __shared__ __align__(16) float As[32][68];
    __shared__ __align__(16) float Bs[32][68];
    __shared__ float sT[64][65];
    int tid = threadIdx.x;
    int h0 = blockIdx.x * 64;
    int n0 = blockIdx.y * 64;     // up to KPAD-64
    int tx = tid & 15, ty = tid >> 4;
    unsigned long long acc[4][2];
#pragma unroll
    for (int r = 0; r < 4; r++) { acc[r][0] = 0ull; acc[r][1] = 0ull; }

    for (int k0 = 0; k0 < DD; k0 += 32) {
        for (int i = tid; i < 64 * 32; i += 256) {
            int k = i & 31, m = i >> 5;
            int n = n0 + m;
            As[k][m] = (n < NN) ? feat[(long long)n * DD + k0 + k] : 0.f;
        }
        for (int i = tid; i < 32 * 64; i += 256) {
            int k = i >> 6, m = i & 63;
            Bs[k][m] = w[(k0 + k) * HH + h0 + m];
        }
        __syncthreads();
#pragma unroll
        for (int k = 0; k < 32; k++) {
            float4 a = *reinterpret_cast<const float4*>(&As[k][ty << 2]);
            double2 bd = *reinterpret_cast<const double2*>(&Bs[k][tx << 2]);
            unsigned long long b0 = d2u(bd.x), b1 = d2u(bd.y);
            unsigned long long a0 = dup2(a.x), a1 = dup2(a.y), a2 = dup2(a.z), a3 = dup2(a.w);
            acc[0][0] = ffma2(a0, b0, acc[0][0]); acc[0][1] = ffma2(a0, b1, acc[0][1]);
            acc[1][0] = ffma2(a1, b0, acc[1][0]); acc[1][1] = ffma2(a1, b1, acc[1][1]);
            acc[2][0] = ffma2(a2, b0, acc[2][0]); acc[2][1] = ffma2(a2, b1, acc[2][1]);
            acc[3][0] = ffma2(a3, b0, acc[3][0]); acc[3][1] = ffma2(a3, b1, acc[3][1]);
        }
        __syncthreads();
    }
#pragma unroll
    for (int r = 0; r < 4; r++) {
        int n = n0 + (ty << 2) + r;
        float2 v0 = up2(acc[r][0]);
        float2 v1 = up2(acc[r][1]);
        float4 o = make_float4(fmaxf(v0.x, 0.f), fmaxf(v0.y, 0.f),
                               fmaxf(v1.x, 0.f), fmaxf(v1.y, 0.f));
        if (n < NN)
            *reinterpret_cast<float4*>(&d_featH[(long long)n * HH + h0 + (tx << 2)]) = o;
        sT[(tx << 2) + 0][(ty << 2) + r] = o.x;
        sT[(tx << 2) + 1][(ty << 2) + r] = o.y;
        sT[(tx << 2) + 2][(ty << 2) + r] = o.z;
        sT[(tx << 2) + 3][(ty << 2) + r] = o.w;
    }
    __syncthreads();
    int hrow = tid >> 2, q = tid & 3;
    size_t gb = (size_t)(h0 + hrow) * KPAD + n0 + q * 16;
    __align__(16) __nv_bfloat16 mhb[16], mlb[16];
    __nv_bfloat16 zero = __float2bfloat16(0.f);
#pragma unroll
    for (int i = 0; i < 16; i++) {
        int n = n0 + q * 16 + i;
        bool mk = (n < NN) && (d_maskf[n] != 0.f);
        float v = sT[hrow][q * 16 + i];
        __nv_bfloat16 h = __float2bfloat16(v);
        mhb[i] = mk ? h : zero;
        mlb[i] = mk ? __float2bfloat16(v - __bfloat162float(h)) : zero;
    }
    *reinterpret_cast<uint4*>(&d_Fhi[gb])     = *reinterpret_cast<uint4*>(&mhb[0]);
    *reinterpret_cast<uint4*>(&d_Fhi[gb + 8]) = *reinterpret_cast<uint4*>(&mhb[8]);
    *reinterpret_cast<uint4*>(&d_Flo[gb])     = *reinterpret_cast<uint4*>(&mlb[0]);
    *reinterpret_cast<uint4*>(&d_Flo[gb + 8]) = *reinterpret_cast<uint4*>(&mlb[8]);
}

// ---------------- launch 3 (ncu slot): Gram, 1024 threads, warp tile 16x32 ----------------
__global__ __launch_bounds__(1024, 1) void gram_hmma_kernel() {
    extern __shared__ __align__(16) char smg[];
    uint32_t sb = smem_to_u32(smg);
    int tid = threadIdx.x;
    int t = blockIdx.x, sp = blockIdx.y;
    int bi = 0;
    while ((bi + 1) * (bi + 2) / 2 <= t) bi++;
    int bj = t - bi * (bi + 1) / 2;
    int h10 = bi * 128, h20 = bj * 128;

    // loader mapping: 8 threads per row (8 x 16B = 128B), 1024 thr = 128 rows
    int lrow = tid >> 3, lseg = tid & 7;
    size_t kstart = (size_t)sp * CPT * 64 + lseg * 8;
    const __nv_bfloat16* pAh = d_Fhi + (size_t)(h10 + lrow) * KPAD + kstart;
    const __nv_bfloat16* pAl = d_Flo + (size_t)(h10 + lrow) * KPAD + kstart;
    const __nv_bfloat16* pBh = d_Fhi + (size_t)(h20 + lrow) * KPAD + kstart;
    const __nv_bfloat16* pBl = d_Flo + (size_t)(h20 + lrow) * KPAD + kstart;
    uint32_t ldst = sb + lrow * GS_ROWB + lseg * 16;

    // compute mapping: 32 warps = 8 (M) x 4 (N); warp tile 16x32
    int wid = tid >> 5, lane = tid & 31;
    int mbase = (wid >> 2) * 16, nbase = (wid & 3) * 32;
    int arow = (lane & 7) + ((lane >> 3) & 1) * 8;
    int acol = ((lane >> 4) & 1) * 8;
    int brow = (lane & 7) + ((lane >> 4) & 1) * 8;
    int bcol = ((lane >> 3) & 1) * 8;
    uint32_t aoff = (uint32_t)(((mbase + arow) * 72 + acol) * 2);
    uint32_t boff[2];
#pragma unroll
    for (int nj = 0; nj < 2; nj++)
        boff[nj] = (uint32_t)(((nbase + nj * 16 + brow) * 72 + bcol) * 2);

    float acc[4][4];
#pragma unroll
    for (int b = 0; b < 4; b++)
#pragma unroll
        for (int c = 0; c < 4; c++) acc[b][c] = 0.f;

    // prologue: stage 0
    CP_ASYNC16(ldst + 0 * GS_TILE, pAh);
    CP_ASYNC16(ldst + 1 * GS_TILE, pAl);
    CP_ASYNC16(ldst + 2 * GS_TILE, pBh);
    CP_ASYNC16(ldst + 3 * GS_TILE, pBl);
    CP_COMMIT();

    for (int c = 0; c < CPT; c++) {
        if (c + 1 < CPT) {
            uint32_t base = ldst + ((c + 1) & 1) * GS_STAGE;
            size_t ko = (size_t)(c + 1) * 64;
            CP_ASYNC16(base + 0 * GS_TILE, pAh + ko);
            CP_ASYNC16(base + 1 * GS_TILE, pAl + ko);
            CP_ASYNC16(base + 2 * GS_TILE, pBh + ko);
            CP_ASYNC16(base + 3 * GS_TILE, pBl + ko);
            CP_COMMIT();
            CP_WAIT1();
        } else {
            CP_WAIT0();
        }
        __syncthreads();
        uint32_t stg = sb + (c & 1) * GS_STAGE;
#pragma unroll
        for (int ks = 0; ks < 4; ks++) {
            uint32_t kb = ks * 32;
            uint32_t ah[4], al[4], bh[4][2], bl[4][2];
            LDSM4(ah, stg + 0 * GS_TILE + aoff + kb);
#pragma unroll
            for (int nj = 0; nj < 2; nj++) {
                uint32_t r[4];
                LDSM4(r, stg + 2 * GS_TILE + boff[nj] + kb);
                bh[nj * 2][0] = r[0]; bh[nj * 2][1] = r[1];
                bh[nj * 2 + 1][0] = r[2]; bh[nj * 2 + 1][1] = r[3];
            }
#pragma unroll
            for (int nj = 0; nj < 4; nj++) MMA16816(acc[nj], ah, bh[nj]);
#pragma unroll
            for (int nj = 0; nj < 2; nj++) {
                uint32_t r[4];
                LDSM4(r, stg + 3 * GS_TILE + boff[nj] + kb);
                bl[nj * 2][0] = r[0]; bl[nj * 2][1] = r[1];
                bl[nj * 2 + 1][0] = r[2]; bl[nj * 2 + 1][1] = r[3];
            }
#pragma unroll
            for (int nj = 0; nj < 4; nj++) MMA16816(acc[nj], ah, bl[nj]);
            LDSM4(al, stg + 1 * GS_TILE + aoff + kb);
#pragma unroll
            for (int nj = 0; nj < 4; nj++) MMA16816(acc[nj], al, bh[nj]);
        }
        __syncthreads();
    }

    // write 128x128 partial tile
    float* out = &d_Spart[(size_t)(sp * NTRI + t) * 128 * 128];
    int g = lane >> 2, q = lane & 3;
#pragma unroll
    for (int nj = 0; nj < 4; nj++) {
        int r0 = mbase + g;
        int cc = nbase + nj * 8 + q * 2;
        *reinterpret_cast<float2*>(&out[r0 * 128 + cc]) =
            make_float2(acc[nj][0], acc[nj][1]);
        *reinterpret_cast<float2*>(&out[(r0 + 8) * 128 + cc]) =
            make_float2(acc[nj][2], acc[nj][3]);
    }
}

// ---------------- reduce split-K partials into d_Gn lower triangle ----------------
__global__ __launch_bounds__(256) void greduce_kernel() {
    int t = blockIdx.x;
    int bi = 0;
    while ((bi + 1) * (bi + 2) / 2 <= t) bi++;
    int bj = t - bi * (bi + 1) / 2;
    for (int i = threadIdx.x; i < 128 * 128 / 4; i += 256) {
        float4 s = make_float4(0.f, 0.f, 0.f, 0.f);
#pragma unroll
        for (int sp = 0; sp < GSPLIT; sp++) {
            float4 v = *reinterpret_cast<const float4*>(
                &d_Spart[(size_t)(sp * NTRI + t) * 128 * 128 + i * 4]);
            s.x += v.x; s.y += v.y; s.z += v.z; s.w += v.w;
        }
        int r = (i * 4) >> 7, c = (i * 4) & 127;
        *reinterpret_cast<float4*>(&d_Gn[(bi * 128 + r) * HH + bj * 128 + c]) = s;
    }
}

// ---------------- Qn partials (branchy: mask mostly zero -> skip loads) ----------------
__global__ __launch_bounds__(256) void qpart_kernel() {
    int h = blockIdx.x * 256 + threadIdx.x;
    int chunk = blockIdx.y;
    int nb = chunk * NPER;
    float a0 = 0, a1 = 0, a2 = 0, a3 = 0, a4 = 0, a5 = 0, a6 = 0;
    for (int t = 0; t < NPER; t++) {
        int n = nb + t;
        float mv = d_maskf[n];
        if (mv != 0.f) {
            float v = d_featH[(long long)n * HH + h];
            int p = d_preds[n];
            a0 += (p == 0) ? v : 0.f;
            a1 += (p == 1) ? v : 0.f;
            a2 += (p == 2) ? v : 0.f;
            a3 += (p == 3) ? v : 0.f;
            a4 += (p == 4) ? v : 0.f;
            a5 += (p == 5) ? v : 0.f;
            a6 += (p == 6) ? v : 0.f;
        }
    }
    int o = (chunk * HH + h) * CC;
    d_Qpart[o + 0] = a0; d_Qpart[o + 1] = a1; d_Qpart[o + 2] = a2; d_Qpart[o + 3] = a3;
    d_Qpart[o + 4] = a4; d_Qpart[o + 5] = a5; d_Qpart[o + 6] = a6;
}

__global__ void qreduce_kernel(const float* __restrict__ Qin) {
    int idx = blockIdx.x * 256 + threadIdx.x;
    if (idx >= HH * CC) return;
    float s = Qin[idx];
    for (int ch = 0; ch < NCHUNK; ch++) s += d_Qpart[ch * HH * CC + idx];
    d_Qn[idx] = s;
}

// ---------------- mirror + Gin + ridge -> fp32 A (two copies) ----------------
__global__ void convm_kernel(const float* __restrict__ Gin) {
    int idx = blockIdx.x * 256 + threadIdx.x;
    int i = idx >> 10, j = idx & 1023;
    float v = (i >= j) ? d_Gn[i * HH + j] : d_Gn[j * HH + i];
    float a = v + Gin[idx] + ((i == j) ? 100.0f : 0.0f);
    d_GA[idx] = a;
    d_Gf[idx] = a;
}

// ---------------- blocked fp32 Cholesky (lower), block = 64 ----------------
__global__ void chol_potf2(int kb) {
    int i = threadIdx.x;
    int off = kb * 64;
    __shared__ float s[64][65];
    for (int j = 0; j < 64; j++) s[i][j] = d_Gf[(off + i) * HH + off + j];
    __syncthreads();
    for (int j = 0; j < 64; j++) {
        if (i == j) s[j][j] = sqrtf(fmaxf(s[j][j], 1e-20f));
        __syncthreads();
        if (i > j) s[i][j] /= s[j][j];
        __syncthreads();
        if (i > j) {
            float lij = s[i][j];
            for (int k = j + 1; k <= i; k++) s[i][k] -= lij * s[k][j];
        }
        __syncthreads();
    }
    for (int j = 0; j <= i; j++) d_Gf[(off + i) * HH + off + j] = s[i][j];
    d_dinvf[off + i] = 1.0f / s[i][i];
}

__global__ __launch_bounds__(256) void chol_trsm(int kb) {
    int off = kb * 64;
    int base = off + 64;
    __shared__ float L[64][65];
    __shared__ float di[64];
    for (int i = threadIdx.x; i < 64 * 64; i += 256)
        L[i >> 6][i & 63] = d_Gf[(off + (i >> 6)) * HH + off + (i & 63)];
    if (threadIdx.x < 64) di[threadIdx.x] = d_dinvf[off + threadIdx.x];
    __syncthreads();
    int r = base + blockIdx.x * 256 + threadIdx.x;
    if (r >= HH) return;
    float* a = &d_Gf[r * HH + off];
    float x[64];
#pragma unroll
    for (int j = 0; j < 64; j++) x[j] = a[j];
#pragma unroll
    for (int j = 0; j < 64; j++) {
        float xj = x[j] * di[j];
        x[j] = xj;
#pragma unroll
        for (int tt = j + 1; tt < 64; tt++) x[tt] -= xj * L[tt][j];
    }
#pragma unroll
    for (int j = 0; j < 64; j++) a[j] = x[j];
}

__global__ __launch_bounds__(256) void chol_syrk(int kb) {
    int off = kb * 64;
    int base = off + 64;
    int i0 = base + blockIdx.y * 32;
    int j0 = base + blockIdx.x * 32;
    if (j0 > i0) return;
    __shared__ float Li[32][65];
    __shared__ float Lj[32][65];
    int tid = threadIdx.x;
    for (int i = tid; i < 32 * 64; i += 256) {
        int ii = i >> 6, t = i & 63;
        Li[ii][t] = d_Gf[(i0 + ii) * HH + off + t];
        Lj[ii][t] = d_Gf[(j0 + ii) * HH + off + t];
    }
    __syncthreads();
    int tx = tid & 31, ty = tid >> 5;
    float acc[4] = {0, 0, 0, 0};
    for (int t = 0; t < 64; t++) {
        float bj = Lj[tx][t];
#pragma unroll
        for (int r = 0; r < 4; r++) acc[r] += Li[(ty << 2) + r][t] * bj;
    }
#pragma unroll
    for (int r = 0; r < 4; r++) {
        int i = i0 + (ty << 2) + r;
        int j = j0 + tx;
        if (j <= i) d_Gf[i * HH + j] -= acc[r];
    }
}

// ---------------- triangular solves: L y = b ; L^T x = y (7 RHS); mode 0: wo=x, 1: wo+=x ----------------
__global__ __launch_bounds__(1024) void chol_solve(int mode) {
    int i = threadIdx.x;
    __shared__ float shy[64][CC];
    float y[CC];
    const float* b = (mode == 0) ? d_Qn : d_res;
#pragma unroll
    for (int c = 0; c < CC; c++) y[c] = b[i * CC + c];
    for (int jb = 0; jb < HH; jb += 64) {
        for (int j = jb; j < jb + 64; j++) {
            if (i == j) {
                float dgl = d_dinvf[j];
#pragma unroll
                for (int c = 0; c < CC; c++) { y[c] *= dgl; shy[j - jb][c] = y[c]; }
            }
            __syncthreads();
            if (i > j && i < jb + 64) {
                float lij = d_Gf[i * HH + j];
#pragma unroll
                for (int c = 0; c < CC; c++) y[c] -= lij * shy[j - jb][c];
            }
            __syncthreads();
        }
        if (i >= jb + 64) {
            for (int t = 0; t < 64; t++) {
                float lij = d_Gf[i * HH + jb + t];
#pragma unroll
                for (int c = 0; c < CC; c++) y[c] -= lij * shy[t][c];
            }
        }
        __syncthreads();
    }
    for (int jb = HH - 64; jb >= 0; jb -= 64) {
        for (int j = jb + 63; j >= jb; j--) {
            if (i == j) {
                float dgl = d_dinvf[j];
#pragma unroll
                for (int c = 0; c < CC; c++) { y[c] *= dgl; shy[j - jb][c] = y[c]; }
            }
            __syncthreads();
            if (i >= jb && i < j) {
                float lji = d_Gf[j * HH + i];
#pragma unroll
                for (int c = 0; c < CC; c++) y[c] -= lji * shy[j - jb][c];
            }
            __syncthreads();
        }
        if (i < jb) {
            for (int t = 0; t < 64; t++) {
                float lji = d_Gf[(jb + t) * HH + i];
#pragma unroll
                for (int c = 0; c < CC; c++) y[c] -= lji * shy[t][c];
            }
        }
        __syncthreads();
    }
    if (mode == 0) {
#pragma unroll
        for (int c = 0; c < CC; c++) d_wo[i * CC + c] = y[c];
    } else {
#pragma unroll
        for (int c = 0; c < CC; c++) d_wo[i * CC + c] += y[c];
    }
}

// ---------------- residual r = Qn - A*wo, fp32 TwoProd + Neumaier compensation ----------------
__global__ __launch_bounds__(256) void resid_kernel() {
    __shared__ float sw[HH * CC];
    int tid = threadIdx.x;
    for (int i = tid; i < HH * CC; i += 256) sw[i] = d_wo[i];
    __syncthreads();
    int wid = tid >> 5, lane = tid & 31;
    int row = blockIdx.x * 8 + wid;
    float s[CC], comp[CC];
#pragma unroll
    for (int c = 0; c < CC; c++) {
        s[c] = (lane == 0) ? d_Qn[row * CC + c] : 0.f;
        comp[c] = 0.f;
    }
    const float* arow = &d_GA[row * HH];
    for (int j = lane; j < HH; j += 32) {
        float na = -arow[j];
#pragma unroll
        for (int c = 0; c < CC; c++) {
            float w = sw[j * CC + c];
            float p = na * w;
            float e = fmaf(na, w, -p);
            float t = s[c] + p;
            float bb = t - s[c];
            float err = (s[c] - (t - bb)) + (p - bb);
            s[c] = t;
            comp[c] += err + e;
        }
    }
#pragma unroll
    for (int c = 0; c < CC; c++) {
#pragma unroll
        for (int off = 16; off > 0; off >>= 1) {
            float s2 = __shfl_xor_sync(0xffffffffu, s[c], off);
            float c2 = __shfl_xor_sync(0xffffffffu, comp[c], off);
            float t = s[c] + s2;
            float bb = t - s[c];
            float err = (s[c] - (t - bb)) + (s2 - bb);
            s[c] = t;
            comp[c] += c2 + err;
        }
    }
    if (lane == 0) {
#pragma unroll
        for (int c = 0; c < CC; c++) d_res[row * CC + c] = s[c] + comp[c];
    }
}

// ---------------- pred_domain = featH @ wo ----------------
__global__ __launch_bounds__(256) void final_kernel(float* __restrict__ out) {
    __shared__ float sw[HH * CC];
    int tid = threadIdx.x;
    for (int i = tid; i < HH * CC; i += 256) sw[i] = d_wo[i];
    __syncthreads();
    int warp = tid >> 5, lane = tid & 31;
    int n = blockIdx.x * 8 + warp;
    if (n >= NN) return;
    const float* a = &d_featH[(long long)n * HH];
    float acc[CC];
#pragma unroll
    for (int c = 0; c < CC; c++) acc[c] = 0.f;
#pragma unroll
    for (int h = lane; h < HH; h += 32) {
        float v = a[h];
#pragma unroll
        for (int c = 0; c < CC; c++) acc[c] += v * sw[h * CC + c];
    }
#pragma unroll
    for (int c = 0; c < CC; c++) {
#pragma unroll
        for (int off = 16; off > 0; off >>= 1)
            acc[c] += __shfl_xor_sync(0xffffffffu, acc[c], off);
    }
    if (lane == 0) {
#pragma unroll
        for (int c = 0; c < CC; c++) out[(long long)n * CC + c] = acc[c];
    }
}

// ---------------- launcher ----------------
extern "C" void kernel_launch(void* const* d_in, const int* in_sizes, int n_in,
                              void* d_out, int out_size) {
    const float* feat   = (const float*)d_in[0];
    const float* proto  = (const float*)d_in[1];
    const float* wrand  = (const float*)d_in[2];
    const float* Qin    = (const float*)d_in[3];
    const float* Gin    = (const float*)d_in[4];
    const float* coords = (const float*)d_in[5];
    const float* normz  = (const float*)d_in[6];
    const void*  nidx   = (const void*)d_in[7];
    float* out = (float*)d_out;

    cudaFuncSetAttribute(gram_hmma_kernel,
                         cudaFuncAttributeMaxDynamicSharedMemorySize, GS_TOTAL);

    preds_kernel<<<(NN + 255) / 256, 256>>>(feat, proto);                 // 0
    mask_kernel<<<(NN + 255) / 256, 256>>>(coords, normz, nidx);          // 1
    feath_kernel<<<dim3(HH / 64, KPAD / 64), 256>>>(feat, wrand);         // 2
    gram_hmma_kernel<<<dim3(NTRI, GSPLIT), 1024, GS_TOTAL>>>();           // 3 <- ncu slot
    greduce_kernel<<<NTRI, 256>>>();
    qpart_kernel<<<dim3(HH / 256, NCHUNK), 256>>>();
    qreduce_kernel<<<(HH * CC + 255) / 256, 256>>>(Qin);
    convm_kernel<<<(HH * HH) / 256, 256>>>(Gin);

    for (int kb = 0; kb < HH / 64; kb++) {
        chol_potf2<<<1, 64>>>(kb);
        int rows = HH - (kb * 64 + 64);
        if (rows > 0) {
            chol_trsm<<<(rows + 255) / 256, 256>>>(kb);
            int nt = (rows + 31) / 32;
            chol_syrk<<<dim3(nt, nt), 256>>>(kb);
        }
    }
    chol_solve<<<1, 1024>>>(0);
    resid_kernel<<<HH / 8, 256>>>();
    chol_solve<<<1, 1024>>>(1);
    final_kernel<<<(NN + 7) / 8, 256>>>(out);
}

// round 14
// speedup vs baseline: 1.6510x; 1.2900x over previous
#include <cuda_runtime.h>
#include <cuda_bf16.h>
#include <math.h>
#include <stdint.h>

#define NN 100000
#define KK 20
#define DD 96
#define HH 1024
#define CC 7
#define KPAD 100096               // capacity for compacted K (worst case all active)
#define GSPLIT 4
#define NTRI 36
#define NCHUNK 32
#define NBLK 391                  // ceil(NN/256)

// gram smem geometry: 4 tiles of 128 rows x 72 bf16, double buffered
#define GS_ROWB 144
#define GS_TILE (128 * GS_ROWB)   // 18432 B
#define GS_STAGE (4 * GS_TILE)    // 73728 B
#define GS_TOTAL (2 * GS_STAGE)   // 147456 B

// ---------------- scratch (static device globals; no allocations) ----------------
static __device__ int           d_preds[NN];
static __device__ float         d_maskf[NN];
static __device__ int           d_bcnt[NBLK];
static __device__ int           d_boff[NBLK];
static __device__ int           d_nact;
static __device__ int           d_nchunk;            // ceil(nact/64)
static __device__ int           d_active[NN];
static __device__ float         d_featH[(long long)NN * HH];   // 400 MB fp32
static __device__ __nv_bfloat16 d_Fhi[(long long)HH * KPAD];   // compacted transposed hi
static __device__ __nv_bfloat16 d_Flo[(long long)HH * KPAD];   // compacted transposed lo
static __device__ float         d_Spart[GSPLIT * NTRI * 128 * 128];
static __device__ float         d_Qpart[NCHUNK * HH * CC];
static __device__ float         d_Qn[HH * CC];
static __device__ float         d_Gn[HH * HH];
static __device__ float         d_GA[HH * HH];
static __device__ float         d_Gf[HH * HH];
static __device__ float         d_dinvf[HH];
static __device__ float         d_res[HH * CC];
static __device__ float         d_wo[HH * CC];

// ---------------- ptx helpers ----------------
__device__ __forceinline__ uint32_t smem_to_u32(const void* smem_ptr) {
    uint32_t addr;
    asm("{ .reg .u64 tmp; cvta.to.shared.u64 tmp, %1; cvt.u32.u64 %0, tmp; }"
        : "=r"(addr) : "l"(smem_ptr));
    return addr;
}
#define CP_ASYNC16(dst, src) \
    asm volatile("cp.async.cg.shared.global [%0], [%1], 16;" :: "r"(dst), "l"(src))
#define CP_COMMIT() asm volatile("cp.async.commit_group;" ::: "memory")
#define CP_WAIT1()  asm volatile("cp.async.wait_group 1;" ::: "memory")
#define CP_WAIT0()  asm volatile("cp.async.wait_group 0;" ::: "memory")
#define LDSM4(r, addr) \
    asm volatile("ldmatrix.sync.aligned.m8n8.x4.shared.b16 {%0,%1,%2,%3}, [%4];" \
        : "=r"((r)[0]), "=r"((r)[1]), "=r"((r)[2]), "=r"((r)[3]) : "r"(addr))
#define MMA16816(c, a, b) \
    asm volatile("mma.sync.aligned.m16n8k16.row.col.f32.bf16.bf16.f32 " \
        "{%0,%1,%2,%3}, {%4,%5,%6,%7}, {%8,%9}, {%0,%1,%2,%3};" \
        : "+f"((c)[0]), "+f"((c)[1]), "+f"((c)[2]), "+f"((c)[3]) \
        : "r"((a)[0]), "r"((a)[1]), "r"((a)[2]), "r"((a)[3]), "r"((b)[0]), "r"((b)[1]))

__device__ __forceinline__ unsigned long long ffma2(unsigned long long a,
                                                    unsigned long long b,
                                                    unsigned long long c) {
    unsigned long long d;
    asm("fma.rn.f32x2 %0, %1, %2, %3;" : "=l"(d) : "l"(a), "l"(b), "l"(c));
    return d;
}
__device__ __forceinline__ unsigned long long dup2(float x) {
    unsigned long long d;
    asm("mov.b64 %0, {%1, %1};" : "=l"(d) : "f"(x));
    return d;
}
__device__ __forceinline__ float2 up2(unsigned long long v) {
    float2 r;
    asm("mov.b64 {%0, %1}, %2;" : "=f"(r.x), "=f"(r.y) : "l"(v));
    return r;
}
__device__ __forceinline__ unsigned long long d2u(double d) {
    return (unsigned long long)__double_as_longlong(d);
}

// ---------------- preds ----------------
__global__ __launch_bounds__(256) void preds_kernel(const float* __restrict__ feat,
                                                    const float* __restrict__ proto) {
    __shared__ float sp[CC][DD];
    int tid = threadIdx.x;
    if (tid < CC) {
        float s = 0.f;
        for (int k = 0; k < DD; k++) { float v = proto[tid * DD + k]; s += v * v; }
        float inv = 1.f / fmaxf(sqrtf(s), 1e-12f);
        for (int k = 0; k < DD; k++) sp[tid][k] = proto[tid * DD + k] * inv;
    }
    __syncthreads();
    int n = blockIdx.x * 256 + tid;
    if (n >= NN) return;
    const float* f = feat + (long long)n * DD;
    float acc[CC];
#pragma unroll
    for (int c = 0; c < CC; c++) acc[c] = 0.f;
#pragma unroll 4
    for (int k = 0; k < DD; k++) {
        float fk = f[k];
#pragma unroll
        for (int c = 0; c < CC; c++) acc[c] += fk * sp[c][k];
    }
    float best = acc[0];
    int bi = 0;
#pragma unroll
    for (int c = 1; c < CC; c++)
        if (acc[c] > best) { best = acc[c]; bi = c; }
    d_preds[n] = bi;
}

// ---------------- mask + per-block count ----------------
__global__ __launch_bounds__(256) void mask_kernel(const float* __restrict__ coords,
                                                   const float* __restrict__ normz,
                                                   const void* __restrict__ nidx) {
    __shared__ int wsum[8];
    int tid = threadIdx.x;
    int n = blockIdx.x * 256 + tid;
    bool mk = false;
    if (n < NN) {
        const int* pw = (const int*)nidx;
        int is64 = 1;
#pragma unroll
        for (int k = 1; k < 40; k += 2) is64 &= (pw[k] == 0);
        int p = d_preds[n];
        const long long* ni64 = (const long long*)nidx;
        const int*       ni32 = (const int*)nidx;
        int cnt = 0;
#pragma unroll
        for (int k = 0; k < KK; k++) {
            long long raw = is64 ? ni64[(long long)n * KK + k]
                                 : (long long)ni32[(long long)n * KK + k];
            unsigned int idx = (unsigned int)raw;
            if (idx >= NN) idx = 0;
            cnt += (d_preds[idx] == p);
        }
        bool cmask = cnt > 16;
        bool plane   = (p == 2) | (p == 3) | (p == 4);
        bool manmade = (p == 5);
        bool other   = (p == 0) | (p == 1) | (p == 6);
        float nz = normz[n];
        float z  = coords[(long long)n * 3 + 2];
        bool ground = plane && (nz > 0.9f) && (z < -10.0f);
        bool g = ground || other || manmade;
        bool m = (manmade && (nz < 0.1f)) || other || plane;
        mk = cmask && g && m;
        d_maskf[n] = mk ? 1.f : 0.f;
    }
    unsigned int b = __ballot_sync(0xffffffffu, mk);
    if ((tid & 31) == 0) wsum[tid >> 5] = __popc(b);
    __syncthreads();
    if (tid == 0) {
        int s = 0;
#pragma unroll
        for (int w = 0; w < 8; w++) s += wsum[w];
        d_bcnt[blockIdx.x] = s;
    }
}

// ---------------- scan block counts -> offsets, totals ----------------
__global__ __launch_bounds__(512) void scan_kernel() {
    __shared__ int s[NBLK];
    int tid = threadIdx.x;
    if (tid < NBLK) s[tid] = d_bcnt[tid];
    __syncthreads();
    if (tid == 0) {
        int run = 0;
        for (int i = 0; i < NBLK; i++) { int v = s[i]; s[i] = run; run += v; }
        d_nact = run;
        d_nchunk = (run + 63) / 64;
    }
    __syncthreads();
    if (tid < NBLK) d_boff[tid] = s[tid];
}

// ---------------- scatter active indices (deterministic ascending order) ----------------
__global__ __launch_bounds__(256) void scatter_kernel() {
    __shared__ int wcnt[8];
    __shared__ int woff[8];
    int tid = threadIdx.x;
    int n = blockIdx.x * 256 + tid;
    bool mk = (n < NN) && (d_maskf[n] != 0.f);
    unsigned int b = __ballot_sync(0xffffffffu, mk);
    int lane = tid & 31, wid = tid >> 5;
    if (lane == 0) wcnt[wid] = __popc(b);
    __syncthreads();
    if (tid == 0) {
        int run = 0;
#pragma unroll
        for (int w = 0; w < 8; w++) { woff[w] = run; run += wcnt[w]; }
    }
    __syncthreads();
    if (mk) {
        int rank = __popc(b & ((1u << lane) - 1u));
        d_active[d_boff[blockIdx.x] + woff[wid] + rank] = n;
    }
}

// ---------------- feat_h = relu(feat @ W) fp32 only (no bf16 epilogue) ----------------
__global__ __launch_bounds__(256) void feath_kernel(const float* __restrict__ feat,
                                                    const float* __restrict__ w) {
    __shared__ __align__(16) float As[32][68];
    __shared__ __align__(16) float Bs[32][68];
    int tid = threadIdx.x;
    int h0 = blockIdx.x * 64;
    int n0 = blockIdx.y * 64;
    int tx = tid & 15, ty = tid >> 4;
    unsigned long long acc[4][2];
#pragma unroll
    for (int r = 0; r < 4; r++) { acc[r][0] = 0ull; acc[r][1] = 0ull; }

    for (int k0 = 0; k0 < DD; k0 += 32) {
        for (int i = tid; i < 64 * 32; i += 256) {
            int k = i & 31, m = i >> 5;
            int n = n0 + m;
            As[k][m] = (n < NN) ? feat[(long long)n * DD + k0 + k] : 0.f;
        }
        for (int i = tid; i < 32 * 64; i += 256) {
            int k = i >> 6, m = i & 63;
            Bs[k][m] = w[(k0 + k) * HH + h0 + m];
        }
        __syncthreads();
#pragma unroll
        for (int k = 0; k < 32; k++) {
            float4 a = *reinterpret_cast<const float4*>(&As[k][ty << 2]);
            double2 bd = *reinterpret_cast<const double2*>(&Bs[k][tx << 2]);
            unsigned long long b0 = d2u(bd.x), b1 = d2u(bd.y);
            unsigned long long a0 = dup2(a.x), a1 = dup2(a.y), a2 = dup2(a.z), a3 = dup2(a.w);
            acc[0][0] = ffma2(a0, b0, acc[0][0]); acc[0][1] = ffma2(a0, b1, acc[0][1]);
            acc[1][0] = ffma2(a1, b0, acc[1][0]); acc[1][1] = ffma2(a1, b1, acc[1][1]);
            acc[2][0] = ffma2(a2, b0, acc[2][0]); acc[2][1] = ffma2(a2, b1, acc[2][1]);
            acc[3][0] = ffma2(a3, b0, acc[3][0]); acc[3][1] = ffma2(a3, b1, acc[3][1]);
        }
        __syncthreads();
    }
#pragma unroll
    for (int r = 0; r < 4; r++) {
        int n = n0 + (ty << 2) + r;
        if (n < NN) {
            float2 v0 = up2(acc[r][0]);
            float2 v1 = up2(acc[r][1]);
            *reinterpret_cast<float4*>(&d_featH[(long long)n * HH + h0 + (tx << 2)]) =
                make_float4(fmaxf(v0.x, 0.f), fmaxf(v0.y, 0.f),
                            fmaxf(v1.x, 0.f), fmaxf(v1.y, 0.f));
        }
    }
}

// ---------------- compact: gather active rows -> transposed bf16 hi/lo ----------------
__global__ __launch_bounds__(256) void compact_kernel() {
    __shared__ float sT[64][65];
    int tid = threadIdx.x;
    int h0 = blockIdx.x * 64;
    int NCH = d_nchunk;
    int nact = d_nact;
    for (int cb = blockIdx.y; cb < NCH; cb += 64) {
        int p0 = cb * 64;
        int pl = tid >> 2, seg = tid & 3;       // pl: local p row 0..63, seg: 16-h segment
        int p = p0 + pl;
        int n = (p < nact) ? d_active[p] : -1;
        // load featH[n][h0+seg*16 .. +16] and stage transposed
        float4 v0, v1, v2, v3;
        if (n >= 0) {
            const float* src = &d_featH[(long long)n * HH + h0 + seg * 16];
            v0 = *reinterpret_cast<const float4*>(src);
            v1 = *reinterpret_cast<const float4*>(src + 4);
            v2 = *reinterpret_cast<const float4*>(src + 8);
            v3 = *reinterpret_cast<const float4*>(src + 12);
        } else {
            v0 = v1 = v2 = v3 = make_float4(0.f, 0.f, 0.f, 0.f);
        }
        __syncthreads();
        {
            int hb = seg * 16;
            sT[hb + 0][pl] = v0.x;  sT[hb + 1][pl] = v0.y;
            sT[hb + 2][pl] = v0.z;  sT[hb + 3][pl] = v0.w;
            sT[hb + 4][pl] = v1.x;  sT[hb + 5][pl] = v1.y;
            sT[hb + 6][pl] = v1.z;  sT[hb + 7][pl] = v1.w;
            sT[hb + 8][pl] = v2.x;  sT[hb + 9][pl] = v2.y;
            sT[hb + 10][pl] = v2.z; sT[hb + 11][pl] = v2.w;
            sT[hb + 12][pl] = v3.x; sT[hb + 13][pl] = v3.y;
            sT[hb + 14][pl] = v3.z; sT[hb + 15][pl] = v3.w;
        }
        __syncthreads();
        {
            int hrow = tid >> 2, q = tid & 3;
            __align__(16) __nv_bfloat16 hb16[16], lb16[16];
#pragma unroll
            for (int i = 0; i < 16; i++) {
                float v = sT[hrow][q * 16 + i];
                __nv_bfloat16 h = __float2bfloat16(v);
                hb16[i] = h;
                lb16[i] = __float2bfloat16(v - __bfloat162float(h));
            }
            size_t gb = (size_t)(h0 + hrow) * KPAD + p0 + q * 16;
            *reinterpret_cast<uint4*>(&d_Fhi[gb])     = *reinterpret_cast<uint4*>(&hb16[0]);
            *reinterpret_cast<uint4*>(&d_Fhi[gb + 8]) = *reinterpret_cast<uint4*>(&hb16[8]);
            *reinterpret_cast<uint4*>(&d_Flo[gb])     = *reinterpret_cast<uint4*>(&lb16[0]);
            *reinterpret_cast<uint4*>(&d_Flo[gb + 8]) = *reinterpret_cast<uint4*>(&lb16[8]);
        }
    }
}

// ---------------- Gram: 1024 threads, dynamic chunk count ----------------
__global__ __launch_bounds__(1024, 1) void gram_hmma_kernel() {
    extern __shared__ __align__(16) char smg[];
    uint32_t sb = smem_to_u32(smg);
    int tid = threadIdx.x;
    int t = blockIdx.x, sp = blockIdx.y;
    int bi = 0;
    while ((bi + 1) * (bi + 2) / 2 <= t) bi++;
    int bj = t - bi * (bi + 1) / 2;
    int h10 = bi * 128, h20 = bj * 128;

    int NCH = d_nchunk;
    int cps = (NCH + GSPLIT - 1) / GSPLIT;
    int c0 = sp * cps;
    int cnt = min(c0 + cps, NCH) - c0;
    float* out = &d_Spart[(size_t)(sp * NTRI + t) * 128 * 128];

    if (cnt <= 0) {
        float4 z = make_float4(0.f, 0.f, 0.f, 0.f);
        for (int i = tid; i < 128 * 128 / 4; i += 1024)
            *reinterpret_cast<float4*>(&out[i * 4]) = z;
        return;
    }

    int lrow = tid >> 3, lseg = tid & 7;
    size_t kstart = (size_t)c0 * 64 + lseg * 8;
    const __nv_bfloat16* pAh = d_Fhi + (size_t)(h10 + lrow) * KPAD + kstart;
    const __nv_bfloat16* pAl = d_Flo + (size_t)(h10 + lrow) * KPAD + kstart;
    const __nv_bfloat16* pBh = d_Fhi + (size_t)(h20 + lrow) * KPAD + kstart;
    const __nv_bfloat16* pBl = d_Flo + (size_t)(h20 + lrow) * KPAD + kstart;
    uint32_t ldst = sb + lrow * GS_ROWB + lseg * 16;

    int wid = tid >> 5, lane = tid & 31;
    int mbase = (wid >> 2) * 16, nbase = (wid & 3) * 32;
    int arow = (lane & 7) + ((lane >> 3) & 1) * 8;
    int acol = ((lane >> 4) & 1) * 8;
    int brow = (lane & 7) + ((lane >> 4) & 1) * 8;
    int bcol = ((lane >> 3) & 1) * 8;
    uint32_t aoff = (uint32_t)(((mbase + arow) * 72 + acol) * 2);
    uint32_t boff[2];
#pragma unroll
    for (int nj = 0; nj < 2; nj++)
        boff[nj] = (uint32_t)(((nbase + nj * 16 + brow) * 72 + bcol) * 2);

    float acc[4][4];
#pragma unroll
    for (int b = 0; b < 4; b++)
#pragma unroll
        for (int c = 0; c < 4; c++) acc[b][c] = 0.f;

    CP_ASYNC16(ldst + 0 * GS_TILE, pAh);
    CP_ASYNC16(ldst + 1 * GS_TILE, pAl);
    CP_ASYNC16(ldst + 2 * GS_TILE, pBh);
    CP_ASYNC16(ldst + 3 * GS_TILE, pBl);
    CP_COMMIT();

    for (int c = 0; c < cnt; c++) {
        if (c + 1 < cnt) {
            uint32_t base = ldst + ((c + 1) & 1) * GS_STAGE;
            size_t ko = (size_t)(c + 1) * 64;
            CP_ASYNC16(base + 0 * GS_TILE, pAh + ko);
            CP_ASYNC16(base + 1 * GS_TILE, pAl + ko);
            CP_ASYNC16(base + 2 * GS_TILE, pBh + ko);
            CP_ASYNC16(base + 3 * GS_TILE, pBl + ko);
            CP_COMMIT();
            CP_WAIT1();
        } else {
            CP_WAIT0();
        }
        __syncthreads();
        uint32_t stg = sb + (c & 1) * GS_STAGE;
#pragma unroll
        for (int ks = 0; ks < 4; ks++) {
            uint32_t kb = ks * 32;
            uint32_t ah[4], al[4], bh[4][2], bl[4][2];
            LDSM4(ah, stg + 0 * GS_TILE + aoff + kb);
#pragma unroll
            for (int nj = 0; nj < 2; nj++) {
                uint32_t r[4];
                LDSM4(r, stg + 2 * GS_TILE + boff[nj] + kb);
                bh[nj * 2][0] = r[0]; bh[nj * 2][1] = r[1];
                bh[nj * 2 + 1][0] = r[2]; bh[nj * 2 + 1][1] = r[3];
            }
#pragma unroll
            for (int nj = 0; nj < 4; nj++) MMA16816(acc[nj], ah, bh[nj]);
#pragma unroll
            for (int nj = 0; nj < 2; nj++) {
                uint32_t r[4];
                LDSM4(r, stg + 3 * GS_TILE + boff[nj] + kb);
                bl[nj * 2][0] = r[0]; bl[nj * 2][1] = r[1];
                bl[nj * 2 + 1][0] = r[2]; bl[nj * 2 + 1][1] = r[3];
            }
#pragma unroll
            for (int nj = 0; nj < 4; nj++) MMA16816(acc[nj], ah, bl[nj]);
            LDSM4(al, stg + 1 * GS_TILE + aoff + kb);
#pragma unroll
            for (int nj = 0; nj < 4; nj++) MMA16816(acc[nj], al, bh[nj]);
        }
        __syncthreads();
    }

    int g = lane >> 2, q = lane & 3;
#pragma unroll
    for (int nj = 0; nj < 4; nj++) {
        int r0 = mbase + g;
        int cc = nbase + nj * 8 + q * 2;
        *reinterpret_cast<float2*>(&out[r0 * 128 + cc]) =
            make_float2(acc[nj][0], acc[nj][1]);
        *reinterpret_cast<float2*>(&out[(r0 + 8) * 128 + cc]) =
            make_float2(acc[nj][2], acc[nj][3]);
    }
}

// ---------------- reduce split-K partials ----------------
__global__ __launch_bounds__(256) void greduce_kernel() {
    int t = blockIdx.x;
    int bi = 0;
    while ((bi + 1) * (bi + 2) / 2 <= t) bi++;
    int bj = t - bi * (bi + 1) / 2;
    for (int i = threadIdx.x; i < 128 * 128 / 4; i += 256) {
        float4 s = make_float4(0.f, 0.f, 0.f, 0.f);
#pragma unroll
        for (int sp = 0; sp < GSPLIT; sp++) {
            float4 v = *reinterpret_cast<const float4*>(
                &d_Spart[(size_t)(sp * NTRI + t) * 128 * 128 + i * 4]);
            s.x += v.x; s.y += v.y; s.z += v.z; s.w += v.w;
        }
        int r = (i * 4) >> 7, c = (i * 4) & 127;
        *reinterpret_cast<float4*>(&d_Gn[(bi * 128 + r) * HH + bj * 128 + c]) = s;
    }
}

// ---------------- Qn partials over active list ----------------
__global__ __launch_bounds__(256) void qpart_kernel() {
    int h = blockIdx.x * 256 + threadIdx.x;
    int chunk = blockIdx.y;
    int nact = d_nact;
    int stride = (nact + NCHUNK - 1) / NCHUNK;
    int p0 = chunk * stride;
    int p1 = min(p0 + stride, nact);
    float a0 = 0, a1 = 0, a2 = 0, a3 = 0, a4 = 0, a5 = 0, a6 = 0;
    for (int p = p0; p < p1; p++) {
        int n = d_active[p];
        float v = d_featH[(long long)n * HH + h];
        int pr = d_preds[n];
        a0 += (pr == 0) ? v : 0.f;
        a1 += (pr == 1) ? v : 0.f;
        a2 += (pr == 2) ? v : 0.f;
        a3 += (pr == 3) ? v : 0.f;
        a4 += (pr == 4) ? v : 0.f;
        a5 += (pr == 5) ? v : 0.f;
        a6 += (pr == 6) ? v : 0.f;
    }
    int o = (chunk * HH + h) * CC;
    d_Qpart[o + 0] = a0; d_Qpart[o + 1] = a1; d_Qpart[o + 2] = a2; d_Qpart[o + 3] = a3;
    d_Qpart[o + 4] = a4; d_Qpart[o + 5] = a5; d_Qpart[o + 6] = a6;
}

__global__ void qreduce_kernel(const float* __restrict__ Qin) {
    int idx = blockIdx.x * 256 + threadIdx.x;
    if (idx >= HH * CC) return;
    float s = Qin[idx];
    for (int ch = 0; ch < NCHUNK; ch++) s += d_Qpart[ch * HH * CC + idx];
    d_Qn[idx] = s;
}

// ---------------- mirror + Gin + ridge -> fp32 A (two copies) ----------------
__global__ void convm_kernel(const float* __restrict__ Gin) {
    int idx = blockIdx.x * 256 + threadIdx.x;
    int i = idx >> 10, j = idx & 1023;
    float v = (i >= j) ? d_Gn[i * HH + j] : d_Gn[j * HH + i];
    float a = v + Gin[idx] + ((i == j) ? 100.0f : 0.0f);
    d_GA[idx] = a;
    d_Gf[idx] = a;
}

// ---------------- blocked fp32 Cholesky (lower), block = 64 ----------------
__global__ void chol_potf2(int kb) {
    int i = threadIdx.x;
    int off = kb * 64;
    __shared__ float s[64][65];
    for (int j = 0; j < 64; j++) s[i][j] = d_Gf[(off + i) * HH + off + j];
    __syncthreads();
    for (int j = 0; j < 64; j++) {
        if (i == j) s[j][j] = sqrtf(fmaxf(s[j][j], 1e-20f));
        __syncthreads();
        if (i > j) s[i][j] /= s[j][j];
        __syncthreads();
        if (i > j) {
            float lij = s[i][j];
            for (int k = j + 1; k <= i; k++) s[i][k] -= lij * s[k][j];
        }
        __syncthreads();
    }
    for (int j = 0; j <= i; j++) d_Gf[(off + i) * HH + off + j] = s[i][j];
    d_dinvf[off + i] = 1.0f / s[i][i];
}

__global__ __launch_bounds__(256) void chol_trsm(int kb) {
    int off = kb * 64;
    int base = off + 64;
    __shared__ float L[64][65];
    __shared__ float di[64];
    for (int i = threadIdx.x; i < 64 * 64; i += 256)
        L[i >> 6][i & 63] = d_Gf[(off + (i >> 6)) * HH + off + (i & 63)];
    if (threadIdx.x < 64) di[threadIdx.x] = d_dinvf[off + threadIdx.x];
    __syncthreads();
    int r = base + blockIdx.x * 256 + threadIdx.x;
    if (r >= HH) return;
    float* a = &d_Gf[r * HH + off];
    float x[64];
#pragma unroll
    for (int j = 0; j < 64; j++) x[j] = a[j];
#pragma unroll
    for (int j = 0; j < 64; j++) {
        float xj = x[j] * di[j];
        x[j] = xj;
#pragma unroll
        for (int tt = j + 1; tt < 64; tt++) x[tt] -= xj * L[tt][j];
    }
#pragma unroll
    for (int j = 0; j < 64; j++) a[j] = x[j];
}

__global__ __launch_bounds__(256) void chol_syrk(int kb) {
    int off = kb * 64;
    int base = off + 64;
    int i0 = base + blockIdx.y * 32;
    int j0 = base + blockIdx.x * 32;
    if (j0 > i0) return;
    __shared__ float Li[32][65];
    __shared__ float Lj[32][65];
    int tid = threadIdx.x;
    for (int i = tid; i < 32 * 64; i += 256) {
        int ii = i >> 6, t = i & 63;
        Li[ii][t] = d_Gf[(i0 + ii) * HH + off + t];
        Lj[ii][t] = d_Gf[(j0 + ii) * HH + off + t];
    }
    __syncthreads();
    int tx = tid & 31, ty = tid >> 5;
    float acc[4] = {0, 0, 0, 0};
    for (int t = 0; t < 64; t++) {
        float bj = Lj[tx][t];
#pragma unroll
        for (int r = 0; r < 4; r++) acc[r] += Li[(ty << 2) + r][t] * bj;
    }
#pragma unroll
    for (int r = 0; r < 4; r++) {
        int i = i0 + (ty << 2) + r;
        int j = j0 + tx;
        if (j <= i) d_Gf[i * HH + j] -= acc[r];
    }
}

// ---------------- triangular solves ----------------
__global__ __launch_bounds__(1024) void chol_solve(int mode) {
    int i = threadIdx.x;
    __shared__ float shy[64][CC];
    float y[CC];
    const float* b = (mode == 0) ? d_Qn : d_res;
#pragma unroll
    for (int c = 0; c < CC; c++) y[c] = b[i * CC + c];
    for (int jb = 0; jb < HH; jb += 64) {
        for (int j = jb; j < jb + 64; j++) {
            if (i == j) {
                float dgl = d_dinvf[j];
#pragma unroll
                for (int c = 0; c < CC; c++) { y[c] *= dgl; shy[j - jb][c] = y[c]; }
            }
            __syncthreads();
            if (i > j && i < jb + 64) {
                float lij = d_Gf[i * HH + j];
#pragma unroll
                for (int c = 0; c < CC; c++) y[c] -= lij * shy[j - jb][c];
            }
            __syncthreads();
        }
        if (i >= jb + 64) {
            for (int t = 0; t < 64; t++) {
                float lij = d_Gf[i * HH + jb + t];
#pragma unroll
                for (int c = 0; c < CC; c++) y[c] -= lij * shy[t][c];
            }
        }
        __syncthreads();
    }
    for (int jb = HH - 64; jb >= 0; jb -= 64) {
        for (int j = jb + 63; j >= jb; j--) {
            if (i == j) {
                float dgl = d_dinvf[j];
#pragma unroll
                for (int c = 0; c < CC; c++) { y[c] *= dgl; shy[j - jb][c] = y[c]; }
            }
            __syncthreads();
            if (i >= jb && i < j) {
                float lji = d_Gf[j * HH + i];
#pragma unroll
                for (int c = 0; c < CC; c++) y[c] -= lji * shy[j - jb][c];
            }
            __syncthreads();
        }
        if (i < jb) {
            for (int t = 0; t < 64; t++) {
                float lji = d_Gf[(jb + t) * HH + i];
#pragma unroll
                for (int c = 0; c < CC; c++) y[c] -= lji * shy[t][c];
            }
        }
        __syncthreads();
    }
    if (mode == 0) {
#pragma unroll
        for (int c = 0; c < CC; c++) d_wo[i * CC + c] = y[c];
    } else {
#pragma unroll
        for (int c = 0; c < CC; c++) d_wo[i * CC + c] += y[c];
    }
}

// ---------------- residual r = Qn - A*wo (compensated) ----------------
__global__ __launch_bounds__(256) void resid_kernel() {
    __shared__ float sw[HH * CC];
    int tid = threadIdx.x;
    for (int i = tid; i < HH * CC; i += 256) sw[i] = d_wo[i];
    __syncthreads();
    int wid = tid >> 5, lane = tid & 31;
    int row = blockIdx.x * 8 + wid;
    float s[CC], comp[CC];
#pragma unroll
    for (int c = 0; c < CC; c++) {
        s[c] = (lane == 0) ? d_Qn[row * CC + c] : 0.f;
        comp[c] = 0.f;
    }
    const float* arow = &d_GA[row * HH];
    for (int j = lane; j < HH; j += 32) {
        float na = -arow[j];
#pragma unroll
        for (int c = 0; c < CC; c++) {
            float w = sw[j * CC + c];
            float p = na * w;
            float e = fmaf(na, w, -p);
            float t = s[c] + p;
            float bb = t - s[c];
            float err = (s[c] - (t - bb)) + (p - bb);
            s[c] = t;
            comp[c] += err + e;
        }
    }
#pragma unroll
    for (int c = 0; c < CC; c++) {
#pragma unroll
        for (int off = 16; off > 0; off >>= 1) {
            float s2 = __shfl_xor_sync(0xffffffffu, s[c], off);
            float c2 = __shfl_xor_sync(0xffffffffu, comp[c], off);
            float t = s[c] + s2;
            float bb = t - s[c];
            float err = (s[c] - (t - bb)) + (s2 - bb);
            s[c] = t;
            comp[c] += c2 + err;
        }
    }
    if (lane == 0) {
#pragma unroll
        for (int c = 0; c < CC; c++) d_res[row * CC + c] = s[c] + comp[c];
    }
}

// ---------------- pred_domain = featH @ wo ----------------
__global__ __launch_bounds__(256) void final_kernel(float* __restrict__ out) {
    __shared__ float sw[HH * CC];
    int tid = threadIdx.x;
    for (int i = tid; i < HH * CC; i += 256) sw[i] = d_wo[i];
    __syncthreads();
    int warp = tid >> 5, lane = tid & 31;
    int n = blockIdx.x * 8 + warp;
    if (n >= NN) return;
    const float* a = &d_featH[(long long)n * HH];
    float acc[CC];
#pragma unroll
    for (int c = 0; c < CC; c++) acc[c] = 0.f;
#pragma unroll
    for (int h = lane; h < HH; h += 32) {
        float v = a[h];
#pragma unroll
        for (int c = 0; c < CC; c++) acc[c] += v * sw[h * CC + c];
    }
#pragma unroll
    for (int c = 0; c < CC; c++) {
#pragma unroll
        for (int off = 16; off > 0; off >>= 1)
            acc[c] += __shfl_xor_sync(0xffffffffu, acc[c], off);
    }
    if (lane == 0) {
#pragma unroll
        for (int c = 0; c < CC; c++) out[(long long)n * CC + c] = acc[c];
    }
}

// ---------------- launcher ----------------
extern "C" void kernel_launch(void* const* d_in, const int* in_sizes, int n_in,
                              void* d_out, int out_size) {
    const float* feat   = (const float*)d_in[0];
    const float* proto  = (const float*)d_in[1];
    const float* wrand  = (const float*)d_in[2];
    const float* Qin    = (const float*)d_in[3];
    const float* Gin    = (const float*)d_in[4];
    const float* coords = (const float*)d_in[5];
    const float* normz  = (const float*)d_in[6];
    const void*  nidx   = (const void*)d_in[7];
    float* out = (float*)d_out;

    cudaFuncSetAttribute(gram_hmma_kernel,
                         cudaFuncAttributeMaxDynamicSharedMemorySize, GS_TOTAL);

    preds_kernel<<<(NN + 255) / 256, 256>>>(feat, proto);
    mask_kernel<<<NBLK, 256>>>(coords, normz, nidx);
    scan_kernel<<<1, 512>>>();
    scatter_kernel<<<NBLK, 256>>>();
    feath_kernel<<<dim3(HH / 64, (NN + 63) / 64), 256>>>(feat, wrand);
    compact_kernel<<<dim3(HH / 64, 64), 256>>>();
    gram_hmma_kernel<<<dim3(NTRI, GSPLIT), 1024, GS_TOTAL>>>();
    greduce_kernel<<<NTRI, 256>>>();
    qpart_kernel<<<dim3(HH / 256, NCHUNK), 256>>>();
    qreduce_kernel<<<(HH * CC + 255) / 256, 256>>>(Qin);
    convm_kernel<<<(HH * HH) / 256, 256>>>(Gin);

    for (int kb = 0; kb < HH / 64; kb++) {
        chol_potf2<<<1, 64>>>(kb);
        int rows = HH - (kb * 64 + 64);
        if (rows > 0) {
            chol_trsm<<<(rows + 255) / 256, 256>>>(kb);
            int nt = (rows + 31) / 32;
            chol_syrk<<<dim3(nt, nt), 256>>>(kb);
        }
    }
    chol_solve<<<1, 1024>>>(0);
    resid_kernel<<<HH / 8, 256>>>();
    chol_solve<<<1, 1024>>>(1);
    final_kernel<<<(NN + 7) / 8, 256>>>(out);
}